// round 5
// baseline (speedup 1.0000x reference)
#include <cuda_runtime.h>
#include <cstdint>

// out[dst] += x[src] for each edge, D_FEAT = 64 fp32, indices int32.
// 16 threads per edge-group; each thread processes U=4 edges strided by
// n_groups (keeps index loads coalesced) -> MLP=4 per thread to hide the
// ~250cyc L2 gather latency. Vector reduction red.global.add.v4.f32.

#define D_FEAT 64
#define CHUNKS 16   // 64 floats / 4 per float4
#define U 4

__global__ void scatter_add_kernel(const float4* __restrict__ x4,
                                   const int* __restrict__ src_idx,
                                   const int* __restrict__ dst_idx,
                                   float* __restrict__ out,
                                   int n_edges, int n_nodes, int n_groups)
{
    long long tid = (long long)blockIdx.x * blockDim.x + threadIdx.x;
    int chunk = (int)(tid & 15);
    long long eg = tid >> 4;            // edge group
    if (eg >= n_groups) return;

    int s[U], d[U];
    int valid[U];
#pragma unroll
    for (int u = 0; u < U; u++) {
        long long e = eg + (long long)u * n_groups;
        valid[u] = (e < n_edges);
        if (valid[u]) {
            s[u] = __ldg(src_idx + e);
            d[u] = __ldg(dst_idx + e);
            if ((unsigned)s[u] >= (unsigned)n_nodes ||
                (unsigned)d[u] >= (unsigned)n_nodes) valid[u] = 0;
        }
    }

    float4 v[U];
#pragma unroll
    for (int u = 0; u < U; u++) {
        if (valid[u]) v[u] = __ldg(x4 + (size_t)s[u] * CHUNKS + chunk);
    }

#pragma unroll
    for (int u = 0; u < U; u++) {
        if (valid[u]) {
            float* dst_ptr = out + (size_t)d[u] * D_FEAT + (size_t)chunk * 4;
            asm volatile("red.global.add.v4.f32 [%0], {%1, %2, %3, %4};"
                         :: "l"(dst_ptr),
                            "f"(v[u].x), "f"(v[u].y), "f"(v[u].z), "f"(v[u].w)
                         : "memory");
        }
    }
}

extern "C" void kernel_launch(void* const* d_in, const int* in_sizes, int n_in,
                              void* d_out, int out_size)
{
    // Role detection by element count: x (6.4M fp32) > edge_index (2.5M int32)
    int xi = 0, ei = 1;
    if (n_in >= 2 && in_sizes[1] > in_sizes[0]) { xi = 1; ei = 0; }

    const float4* x4 = (const float4*)d_in[xi];
    const int* edge_index = (const int*)d_in[ei];

    int n_edges = in_sizes[ei] / 2;
    int n_nodes = in_sizes[xi] / D_FEAT;
    int n_groups = (n_edges + U - 1) / U;

    const int* src_idx = edge_index;            // row 0
    const int* dst_idx = edge_index + n_edges;  // row 1

    float* out = (float*)d_out;

    // Output is poisoned 0xAA -> zero it first (capturable memset)
    cudaMemsetAsync(out, 0, (size_t)out_size * sizeof(float));

    long long total = (long long)n_groups * CHUNKS;
    int threads = 256;
    int blocks = (int)((total + threads - 1) / threads);
    scatter_add_kernel<<<blocks, threads>>>(x4, src_idx, dst_idx, out,
                                            n_edges, n_nodes, n_groups);
}

// round 6
// speedup vs baseline: 1.5698x; 1.5698x over previous
#include <cuda_runtime.h>
#include <cstdint>

// Two-phase: (1) build CSR grouped by dst (counting sort: histogram + scan +
// scatter), (2) per-node gather-reduce: acc in registers, ONE non-atomic write
// per output row. Removes 320MB of LTS atomic traffic vs scatter-add version.

#define D_FEAT 64
#define CHUNKS 16

#define MAX_NODES 131072
#define MAX_EDGES 1310720
#define SCAN_BLOCK 1024
#define MAX_SCAN_BLOCKS 128   // MAX_NODES / SCAN_BLOCK

__device__ int g_deg[MAX_NODES];
__device__ int g_off[MAX_NODES + 1];
__device__ int g_cnt[MAX_NODES];
__device__ int g_blocksum[MAX_SCAN_BLOCKS];
__device__ int g_blockbase[MAX_SCAN_BLOCKS];
__device__ int g_elist[MAX_EDGES];

// ---------------- CSR build ----------------

__global__ void zero_kernel(int n_nodes) {
    int i = blockIdx.x * blockDim.x + threadIdx.x;
    if (i < n_nodes) { g_deg[i] = 0; g_cnt[i] = 0; }
}

__global__ void hist_kernel(const int* __restrict__ dst, int n_edges, int n_nodes) {
    int e = blockIdx.x * blockDim.x + threadIdx.x;
    if (e >= n_edges) return;
    int d = __ldg(dst + e);
    if ((unsigned)d < (unsigned)n_nodes) atomicAdd(&g_deg[d], 1);
}

__global__ void scanA_kernel(int n_nodes) {          // per-block sums
    __shared__ int sd[SCAN_BLOCK];
    int i = blockIdx.x * SCAN_BLOCK + threadIdx.x;
    sd[threadIdx.x] = (i < n_nodes) ? g_deg[i] : 0;
    __syncthreads();
    for (int s = SCAN_BLOCK / 2; s > 0; s >>= 1) {
        if (threadIdx.x < s) sd[threadIdx.x] += sd[threadIdx.x + s];
        __syncthreads();
    }
    if (threadIdx.x == 0) g_blocksum[blockIdx.x] = sd[0];
}

__global__ void scanB_kernel(int nblocks, int n_nodes, int n_edges) {  // 1 block
    __shared__ int sd[MAX_SCAN_BLOCKS];
    int t = threadIdx.x;
    int v = (t < nblocks) ? g_blocksum[t] : 0;
    sd[t] = v;
    __syncthreads();
    for (int s = 1; s < MAX_SCAN_BLOCKS; s <<= 1) {
        int add = (t >= s) ? sd[t - s] : 0;
        __syncthreads();
        sd[t] += add;
        __syncthreads();
    }
    if (t < nblocks) g_blockbase[t] = sd[t] - v;     // exclusive
    if (t == 0) g_off[n_nodes] = n_edges;
}

__global__ void scanC_kernel(int n_nodes) {          // final exclusive offsets
    __shared__ int sd[SCAN_BLOCK];
    int i = blockIdx.x * SCAN_BLOCK + threadIdx.x;
    int v = (i < n_nodes) ? g_deg[i] : 0;
    sd[threadIdx.x] = v;
    __syncthreads();
    for (int s = 1; s < SCAN_BLOCK; s <<= 1) {
        int add = (threadIdx.x >= s) ? sd[threadIdx.x - s] : 0;
        __syncthreads();
        sd[threadIdx.x] += add;
        __syncthreads();
    }
    if (i < n_nodes) g_off[i] = g_blockbase[blockIdx.x] + sd[threadIdx.x] - v;
}

__global__ void scatter_edges_kernel(const int* __restrict__ src,
                                     const int* __restrict__ dst,
                                     int n_edges, int n_nodes) {
    int e = blockIdx.x * blockDim.x + threadIdx.x;
    if (e >= n_edges) return;
    int s = __ldg(src + e);
    int d = __ldg(dst + e);
    if ((unsigned)s >= (unsigned)n_nodes || (unsigned)d >= (unsigned)n_nodes) return;
    int pos = g_off[d] + atomicAdd(&g_cnt[d], 1);
    g_elist[pos] = s;
}

// ---------------- gather-reduce ----------------
// 16 lanes per node; each lane owns one float4 chunk of the 64-float row.
// 2-deep unroll for modest MLP without front-batched L1tex queue pressure.

__global__ void aggregate_kernel(const float4* __restrict__ x4,
                                 float4* __restrict__ out4,
                                 int n_nodes) {
    long long tid = (long long)blockIdx.x * blockDim.x + threadIdx.x;
    int chunk = (int)(tid & 15);
    long long node = tid >> 4;
    if (node >= n_nodes) return;

    int beg = g_off[node];
    int end = g_off[node + 1];

    float4 a0 = make_float4(0.f, 0.f, 0.f, 0.f);
    float4 a1 = make_float4(0.f, 0.f, 0.f, 0.f);

    int e = beg;
    for (; e + 2 <= end; e += 2) {
        int s0 = __ldg(g_elist + e);
        int s1 = __ldg(g_elist + e + 1);
        float4 v0 = __ldg(x4 + (size_t)s0 * CHUNKS + chunk);
        float4 v1 = __ldg(x4 + (size_t)s1 * CHUNKS + chunk);
        a0.x += v0.x; a0.y += v0.y; a0.z += v0.z; a0.w += v0.w;
        a1.x += v1.x; a1.y += v1.y; a1.z += v1.z; a1.w += v1.w;
    }
    if (e < end) {
        int s0 = __ldg(g_elist + e);
        float4 v0 = __ldg(x4 + (size_t)s0 * CHUNKS + chunk);
        a0.x += v0.x; a0.y += v0.y; a0.z += v0.z; a0.w += v0.w;
    }

    a0.x += a1.x; a0.y += a1.y; a0.z += a1.z; a0.w += a1.w;
    out4[(size_t)node * CHUNKS + chunk] = a0;
}

// ---------------- fallback: proven atomic scatter (R4) ----------------

__global__ void scatter_add_kernel(const float4* __restrict__ x4,
                                   const int* __restrict__ src_idx,
                                   const int* __restrict__ dst_idx,
                                   float* __restrict__ out,
                                   int n_edges, int n_nodes) {
    long long tid = (long long)blockIdx.x * blockDim.x + threadIdx.x;
    long long edge = tid >> 4;
    int chunk = (int)(tid & 15);
    if (edge >= n_edges) return;
    int s = __ldg(src_idx + edge);
    int d = __ldg(dst_idx + edge);
    if ((unsigned)s >= (unsigned)n_nodes || (unsigned)d >= (unsigned)n_nodes) return;
    float4 v = __ldg(x4 + (size_t)s * CHUNKS + chunk);
    float* dst_ptr = out + (size_t)d * D_FEAT + (size_t)chunk * 4;
    asm volatile("red.global.add.v4.f32 [%0], {%1, %2, %3, %4};"
                 :: "l"(dst_ptr), "f"(v.x), "f"(v.y), "f"(v.z), "f"(v.w)
                 : "memory");
}

extern "C" void kernel_launch(void* const* d_in, const int* in_sizes, int n_in,
                              void* d_out, int out_size)
{
    // Role detection by element count: x (6.4M fp32) > edge_index (2.5M int32)
    int xi = 0, ei = 1;
    if (n_in >= 2 && in_sizes[1] > in_sizes[0]) { xi = 1; ei = 0; }

    const float4* x4 = (const float4*)d_in[xi];
    const int* edge_index = (const int*)d_in[ei];

    int n_edges = in_sizes[ei] / 2;
    int n_nodes = in_sizes[xi] / D_FEAT;

    const int* src_idx = edge_index;            // row 0
    const int* dst_idx = edge_index + n_edges;  // row 1

    if (n_nodes > MAX_NODES || n_edges > MAX_EDGES) {
        // Fallback: atomic scatter-add (known-good, 72.4us)
        float* out = (float*)d_out;
        cudaMemsetAsync(out, 0, (size_t)out_size * sizeof(float));
        long long total = (long long)n_edges * CHUNKS;
        int blocks = (int)((total + 255) / 256);
        scatter_add_kernel<<<blocks, 256>>>(x4, src_idx, dst_idx, out,
                                            n_edges, n_nodes);
        return;
    }

    int nblocks_scan = (n_nodes + SCAN_BLOCK - 1) / SCAN_BLOCK;

    zero_kernel<<<(n_nodes + 255) / 256, 256>>>(n_nodes);
    hist_kernel<<<(n_edges + 255) / 256, 256>>>(dst_idx, n_edges, n_nodes);
    scanA_kernel<<<nblocks_scan, SCAN_BLOCK>>>(n_nodes);
    scanB_kernel<<<1, MAX_SCAN_BLOCKS>>>(nblocks_scan, n_nodes, n_edges);
    scanC_kernel<<<nblocks_scan, SCAN_BLOCK>>>(n_nodes);
    scatter_edges_kernel<<<(n_edges + 255) / 256, 256>>>(src_idx, dst_idx,
                                                         n_edges, n_nodes);

    long long total = (long long)n_nodes * CHUNKS;
    int blocks = (int)((total + 255) / 256);
    aggregate_kernel<<<blocks, 256>>>(x4, (float4*)d_out, n_nodes);
}

// round 7
// speedup vs baseline: 1.9335x; 1.2317x over previous
#include <cuda_runtime.h>
#include <cstdint>

// Phase 1: bucket edges by dst (fixed capacity CAP per node) in ONE kernel:
//   pos = atomicAdd(cnt[d],1); elist[d*CAP+pos] = s; overflow -> red.add direct.
// Phase 2: warp-per-node gather-reduce, one red.add.v4 per output chunk.
// Replaces the 6-launch histogram+scan CSR build (~25us) with ~10us.

#define D_FEAT 64
#define CHUNKS 16
#define CAP 64            // Poisson(12.5) max in-degree ~40; overflow handled anyway

#define MAX_NODES 131072
#define MAX_EDGES 2097152

__device__ int g_cnt[MAX_NODES];
__device__ int g_elist[MAX_NODES * CAP];

// ---------------- build buckets ----------------

__global__ void bucket_kernel(const int* __restrict__ src,
                              const int* __restrict__ dst,
                              const float4* __restrict__ x4,
                              float* __restrict__ out,
                              int n_edges, int n_nodes)
{
    int e = blockIdx.x * blockDim.x + threadIdx.x;
    if (e >= n_edges) return;
    int s = __ldg(src + e);
    int d = __ldg(dst + e);
    if ((unsigned)s >= (unsigned)n_nodes || (unsigned)d >= (unsigned)n_nodes) return;

    int pos = atomicAdd(&g_cnt[d], 1);
    if (pos < CAP) {
        g_elist[(size_t)d * CAP + pos] = s;
    } else {
        // overflow (astronomically rare): add this edge directly into out
        // (out is pre-zeroed; aggregate also uses red.add -> commutative, correct)
        const float4* xr = x4 + (size_t)s * CHUNKS;
        float* orow = out + (size_t)d * D_FEAT;
#pragma unroll
        for (int c = 0; c < CHUNKS; c++) {
            float4 v = __ldg(xr + c);
            asm volatile("red.global.add.v4.f32 [%0], {%1, %2, %3, %4};"
                         :: "l"(orow + c * 4), "f"(v.x), "f"(v.y), "f"(v.z), "f"(v.w)
                         : "memory");
        }
    }
}

// ---------------- warp-per-node gather-reduce ----------------
// lane = 2 halves (edge-parallel) x 16 chunks. Fold halves with 4 shfls.

__global__ void aggregate_kernel(const float4* __restrict__ x4,
                                 float* __restrict__ out,
                                 int n_nodes)
{
    int warp = (blockIdx.x * blockDim.x + threadIdx.x) >> 5;
    if (warp >= n_nodes) return;
    int lane = threadIdx.x & 31;
    int chunk = lane & 15;
    int half = lane >> 4;

    int deg = g_cnt[warp];
    if (deg > CAP) deg = CAP;          // overflow edges already added directly
    const int* bucket = g_elist + (size_t)warp * CAP;

    float4 a = make_float4(0.f, 0.f, 0.f, 0.f);
#pragma unroll 2
    for (int e = half; e < deg; e += 2) {
        int s = __ldg(bucket + e);
        float4 v = __ldg(x4 + (size_t)s * CHUNKS + chunk);
        a.x += v.x; a.y += v.y; a.z += v.z; a.w += v.w;
    }

    // fold the two halves (lane i gets lane i+16's accumulator)
    a.x += __shfl_down_sync(0xffffffffu, a.x, 16);
    a.y += __shfl_down_sync(0xffffffffu, a.y, 16);
    a.z += __shfl_down_sync(0xffffffffu, a.z, 16);
    a.w += __shfl_down_sync(0xffffffffu, a.w, 16);

    if (half == 0) {
        float* dst_ptr = out + (size_t)warp * D_FEAT + (size_t)chunk * 4;
        asm volatile("red.global.add.v4.f32 [%0], {%1, %2, %3, %4};"
                     :: "l"(dst_ptr), "f"(a.x), "f"(a.y), "f"(a.z), "f"(a.w)
                     : "memory");
    }
}

// ---------------- fallback: proven atomic scatter (R4, 72us) ----------------

__global__ void scatter_add_kernel(const float4* __restrict__ x4,
                                   const int* __restrict__ src_idx,
                                   const int* __restrict__ dst_idx,
                                   float* __restrict__ out,
                                   int n_edges, int n_nodes)
{
    long long tid = (long long)blockIdx.x * blockDim.x + threadIdx.x;
    long long edge = tid >> 4;
    int chunk = (int)(tid & 15);
    if (edge >= n_edges) return;
    int s = __ldg(src_idx + edge);
    int d = __ldg(dst_idx + edge);
    if ((unsigned)s >= (unsigned)n_nodes || (unsigned)d >= (unsigned)n_nodes) return;
    float4 v = __ldg(x4 + (size_t)s * CHUNKS + chunk);
    float* dst_ptr = out + (size_t)d * D_FEAT + (size_t)chunk * 4;
    asm volatile("red.global.add.v4.f32 [%0], {%1, %2, %3, %4};"
                 :: "l"(dst_ptr), "f"(v.x), "f"(v.y), "f"(v.z), "f"(v.w)
                 : "memory");
}

extern "C" void kernel_launch(void* const* d_in, const int* in_sizes, int n_in,
                              void* d_out, int out_size)
{
    // Role detection by element count: x (6.4M fp32) > edge_index (2.5M int32)
    int xi = 0, ei = 1;
    if (n_in >= 2 && in_sizes[1] > in_sizes[0]) { xi = 1; ei = 0; }

    const float4* x4 = (const float4*)d_in[xi];
    const int* edge_index = (const int*)d_in[ei];

    int n_edges = in_sizes[ei] / 2;
    int n_nodes = in_sizes[xi] / D_FEAT;

    const int* src_idx = edge_index;            // row 0
    const int* dst_idx = edge_index + n_edges;  // row 1

    float* out = (float*)d_out;

    if (n_nodes > MAX_NODES || n_edges > MAX_EDGES) {
        cudaMemsetAsync(out, 0, (size_t)out_size * sizeof(float));
        long long total = (long long)n_edges * CHUNKS;
        scatter_add_kernel<<<(int)((total + 255) / 256), 256>>>(
            x4, src_idx, dst_idx, out, n_edges, n_nodes);
        return;
    }

    void* cnt_ptr = nullptr;
    cudaGetSymbolAddress(&cnt_ptr, g_cnt);

    cudaMemsetAsync(out, 0, (size_t)out_size * sizeof(float));
    cudaMemsetAsync(cnt_ptr, 0, (size_t)n_nodes * sizeof(int));

    bucket_kernel<<<(n_edges + 255) / 256, 256>>>(src_idx, dst_idx, x4, out,
                                                  n_edges, n_nodes);

    long long total = (long long)n_nodes * 32;
    aggregate_kernel<<<(int)((total + 255) / 256), 256>>>(x4, out, n_nodes);
}